// round 2
// baseline (speedup 1.0000x reference)
#include <cuda_runtime.h>
#include <cuda_bf16.h>
#include <math.h>

// Problem constants
#define EMBED  512
#define HIDDEN 512
#define VOCAB  10000
#define BATCH  64
#define SEQT   32
#define GATES  (4 * HIDDEN)   // 2048
#define MROWS  (SEQT * BATCH) // 2048

// ---------------- scratch (device globals; no allocation allowed) -------------
__device__ __align__(16) float g_xs[MROWS * EMBED];       // 4 MB   xs[t*B+b][e]
__device__ __align__(16) float g_xgates[MROWS * GATES];   // 16 MB  xg[t*B+b][g]
__device__ __align__(16) float g_h[BATCH * HIDDEN];
__device__ __align__(16) float g_c[BATCH * HIDDEN];
__device__ __align__(16) float g_hs[SEQT * BATCH * HIDDEN]; // 4 MB hs[t][b][j]
__device__ int g_cap_is64;   // 1 if captions buffer is int64, 0 if int32

// ---------------- captions dtype detection ------------------------------------
// Tokens are in [0, VOCAB). If the buffer is int64, every 8-byte word is a
// valid token (high 32 bits zero). If it is int32, some 8-byte word has a
// nonzero high half (two packed tokens). Deterministic for fixed input.
__global__ void detect_captions_kernel(const void* __restrict__ captions)
{
    const long long* c64 = (const long long*)captions;
    int bad = 0;
    // BATCH*SEQT = 2048 elements if int64; scan all 2048 8-byte words.
    for (int i = threadIdx.x; i < BATCH * SEQT; i += 32) {
        long long v = c64[i];
        if (v < 0 || v >= VOCAB) bad = 1;
    }
    // warp-reduce OR
    #pragma unroll
    for (int s = 16; s > 0; s >>= 1)
        bad |= __shfl_xor_sync(0xffffffffu, bad, s);
    if (threadIdx.x == 0) g_cap_is64 = bad ? 0 : 1;
}

// ---------------- gather: build xs -------------------------------------------
// row m = t*64 + b.  t==0 -> features[b], else emb_table[captions[b][t-1]]
__global__ void gather_xs_kernel(const float* __restrict__ features,
                                 const void* __restrict__ captions,
                                 const float* __restrict__ emb_table)
{
    int m = blockIdx.x;            // 0..2047
    int t = m >> 6;
    int b = m & 63;
    const float* src;
    if (t == 0) {
        src = features + (size_t)b * EMBED;
    } else {
        int idx = b * SEQT + (t - 1);
        long long tok;
        if (g_cap_is64)
            tok = ((const long long*)captions)[idx];
        else
            tok = (long long)((const int*)captions)[idx];
        // safety clamp (also keeps a wrong guess non-fatal)
        if (tok < 0) tok = 0;
        if (tok >= VOCAB) tok = VOCAB - 1;
        src = emb_table + (size_t)tok * EMBED;
    }
    float4* dst = (float4*)(g_xs + (size_t)m * EMBED);
    const float4* s4 = (const float4*)src;
    dst[threadIdx.x] = s4[threadIdx.x];   // 128 threads * float4 = 512 floats
}

// ---------------- generic tiled SGEMM: C = A * B^T (+bias1+bias2) -------------
// A: MxK row-major, B: NxK row-major.  TILE 64x64, 256 thr, 4x4 micro, TK=16.
// mode 0: C[m*N+n]
// mode 1: m = t*64+b  ->  C[(b*32+t)*N + n]   (FC output permute)
__global__ void gemm64_kernel(const float* __restrict__ A,
                              const float* __restrict__ B,
                              float* __restrict__ C,
                              int M, int N, int K,
                              const float* __restrict__ bias1,
                              const float* __restrict__ bias2,
                              int mode)
{
    __shared__ float sA[16][65];
    __shared__ float sB[16][65];

    const int m0 = blockIdx.y * 64;
    const int n0 = blockIdx.x * 64;
    const int tid = threadIdx.x;            // 0..255
    const int tx = tid & 15;                // col group
    const int ty = tid >> 4;                // row group

    const int li = tid >> 2;                // 0..63 row within tile
    const int lk = (tid & 3) * 4;           // 0,4,8,12

    float acc[4][4];
    #pragma unroll
    for (int r = 0; r < 4; r++)
        #pragma unroll
        for (int c = 0; c < 4; c++) acc[r][c] = 0.0f;

    for (int k0 = 0; k0 < K; k0 += 16) {
        // load A tile (M always multiple of 64 here)
        float4 av = *(const float4*)&A[(size_t)(m0 + li) * K + k0 + lk];
        sA[lk + 0][li] = av.x; sA[lk + 1][li] = av.y;
        sA[lk + 2][li] = av.z; sA[lk + 3][li] = av.w;
        // load B tile with N guard
        float4 bv = make_float4(0.f, 0.f, 0.f, 0.f);
        int brow = n0 + li;
        if (brow < N) bv = *(const float4*)&B[(size_t)brow * K + k0 + lk];
        sB[lk + 0][li] = bv.x; sB[lk + 1][li] = bv.y;
        sB[lk + 2][li] = bv.z; sB[lk + 3][li] = bv.w;
        __syncthreads();

        #pragma unroll
        for (int kk = 0; kk < 16; kk++) {
            float a[4], b[4];
            #pragma unroll
            for (int r = 0; r < 4; r++) a[r] = sA[kk][ty * 4 + r];
            #pragma unroll
            for (int c = 0; c < 4; c++) b[c] = sB[kk][tx * 4 + c];
            #pragma unroll
            for (int r = 0; r < 4; r++)
                #pragma unroll
                for (int c = 0; c < 4; c++)
                    acc[r][c] = fmaf(a[r], b[c], acc[r][c]);
        }
        __syncthreads();
    }

    #pragma unroll
    for (int r = 0; r < 4; r++) {
        int m = m0 + ty * 4 + r;
        size_t out_row;
        if (mode == 0) {
            out_row = (size_t)m;
        } else {
            int b = m & 63;
            int t = m >> 6;
            out_row = (size_t)(b * SEQT + t);
        }
        #pragma unroll
        for (int c = 0; c < 4; c++) {
            int n = n0 + tx * 4 + c;
            if (n < N) {
                float v = acc[r][c];
                if (bias1) v += bias1[n];
                if (bias2) v += bias2[n];
                C[out_row * (size_t)N + n] = v;
            }
        }
    }
}

// ---------------- fused LSTM step --------------------------------------------
// grid: (16 j-tiles of 32, 4 b-tiles of 16), block 128 = 32(tx=j) x 4(ty)
// each thread: j = j-tile*32+tx, handles b = b0 + ty*4 + {0..3}, all 4 gates.
__device__ __forceinline__ float sigmoidf_(float x) {
    return 1.0f / (1.0f + expf(-x));
}

__global__ void lstm_step_kernel(const float* __restrict__ W_hh, int t)
{
    const int tx = threadIdx.x & 31;
    const int ty = threadIdx.x >> 5;
    const int j  = blockIdx.x * 32 + tx;
    const int b0 = blockIdx.y * 16;

    float acc[4][4];   // [gate][r]
    #pragma unroll
    for (int g = 0; g < 4; g++)
        #pragma unroll
        for (int r = 0; r < 4; r++) acc[g][r] = 0.0f;

    if (t > 0) {
        __shared__ float hsh[16][33];    // b-tile x k-chunk
        __shared__ float wsh[128][33];   // (gate*32 + jl) x k-chunk

        for (int k0 = 0; k0 < HIDDEN; k0 += 32) {
            // load h tile: 16 b x 32 k = 512 floats, 128 thr -> 1 float4 each
            {
                int idx = threadIdx.x;          // 0..127
                int bb = idx >> 3;              // 0..15
                int kq = (idx & 7) * 4;         // 0..28
                float4 v = *(const float4*)&g_h[(size_t)(b0 + bb) * HIDDEN + k0 + kq];
                hsh[bb][kq + 0] = v.x; hsh[bb][kq + 1] = v.y;
                hsh[bb][kq + 2] = v.z; hsh[bb][kq + 3] = v.w;
            }
            // load W tile: 128 rows x 32 k = 1024 float4 / 128 thr = 8 each
            #pragma unroll
            for (int e = 0; e < 8; e++) {
                int idx = threadIdx.x + 128 * e;   // 0..1023
                int row = idx >> 3;                 // 0..127 = g*32 + jl
                int kq  = (idx & 7) * 4;
                int g   = row >> 5;
                int jl  = row & 31;
                int grow = g * HIDDEN + blockIdx.x * 32 + jl;
                float4 v = *(const float4*)&W_hh[(size_t)grow * HIDDEN + k0 + kq];
                wsh[row][kq + 0] = v.x; wsh[row][kq + 1] = v.y;
                wsh[row][kq + 2] = v.z; wsh[row][kq + 3] = v.w;
            }
            __syncthreads();

            #pragma unroll
            for (int kk = 0; kk < 32; kk++) {
                float hv[4];
                #pragma unroll
                for (int r = 0; r < 4; r++) hv[r] = hsh[ty * 4 + r][kk];
                #pragma unroll
                for (int g = 0; g < 4; g++) {
                    float wv = wsh[g * 32 + tx][kk];
                    #pragma unroll
                    for (int r = 0; r < 4; r++)
                        acc[g][r] = fmaf(wv, hv[r], acc[g][r]);
                }
            }
            __syncthreads();
        }
    }

    const float* xg = g_xgates + (size_t)t * BATCH * GATES;
    float* hs_t = g_hs + (size_t)t * BATCH * HIDDEN;

    #pragma unroll
    for (int r = 0; r < 4; r++) {
        int b = b0 + ty * 4 + r;
        size_t gbase = (size_t)b * GATES + j;
        float gi = acc[0][r] + xg[gbase];
        float gf = acc[1][r] + xg[gbase + HIDDEN];
        float gg = acc[2][r] + xg[gbase + 2 * HIDDEN];
        float go = acc[3][r] + xg[gbase + 3 * HIDDEN];

        float i_ = sigmoidf_(gi);
        float f_ = sigmoidf_(gf);
        float g_ = tanhf(gg);
        float o_ = sigmoidf_(go);

        size_t hidx = (size_t)b * HIDDEN + j;
        float cold = (t == 0) ? 0.0f : g_c[hidx];
        float cn = f_ * cold + i_ * g_;
        float hn = o_ * tanhf(cn);
        g_c[hidx] = cn;
        g_h[hidx] = hn;
        hs_t[hidx] = hn;
    }
}

// ---------------- launch ------------------------------------------------------
extern "C" void kernel_launch(void* const* d_in, const int* in_sizes, int n_in,
                              void* d_out, int out_size)
{
    const float*     features  = (const float*)d_in[0];
    const void*      captions  = d_in[1];            // int32 or int64, detected
    const float*     emb_table = (const float*)d_in[2];
    const float*     W_ih      = (const float*)d_in[3];
    const float*     W_hh      = (const float*)d_in[4];
    const float*     b_ih      = (const float*)d_in[5];
    const float*     b_hh      = (const float*)d_in[6];
    const float*     W_fc      = (const float*)d_in[7];
    const float*     b_fc      = (const float*)d_in[8];
    float*           out       = (float*)d_out;

    float* xs_p;     cudaGetSymbolAddress((void**)&xs_p, g_xs);
    float* xg_p;     cudaGetSymbolAddress((void**)&xg_p, g_xgates);
    float* hs_p;     cudaGetSymbolAddress((void**)&hs_p, g_hs);

    // 0) detect captions dtype (int32 vs int64)
    detect_captions_kernel<<<1, 32>>>(captions);

    // 1) gather xs
    gather_xs_kernel<<<MROWS, 128>>>(features, captions, emb_table);

    // 2) x_gates = xs @ W_ih^T + b_ih + b_hh   (M=2048, N=2048, K=512)
    {
        dim3 grid(GATES / 64, MROWS / 64);
        gemm64_kernel<<<grid, 256>>>(xs_p, W_ih, xg_p,
                                     MROWS, GATES, EMBED, b_ih, b_hh, 0);
    }

    // 3) 32 recurrent steps
    {
        dim3 grid(HIDDEN / 32, BATCH / 16);
        for (int t = 0; t < SEQT; t++)
            lstm_step_kernel<<<grid, 128>>>(W_hh, t);
    }

    // 4) logits = hs @ W_fc^T + b_fc, permuted to (b, t, v)
    {
        dim3 grid((VOCAB + 63) / 64, MROWS / 64);
        gemm64_kernel<<<grid, 256>>>(hs_p, W_fc, out,
                                     MROWS, VOCAB, HIDDEN, b_fc, nullptr, 1);
    }
}

// round 5
// speedup vs baseline: 1.5624x; 1.5624x over previous
#include <cuda_runtime.h>
#include <cuda_bf16.h>
#include <math.h>
#include <stdint.h>

// Problem constants
#define EMBED  512
#define HIDDEN 512
#define VOCAB  10000
#define BATCH  64
#define SEQT   32
#define GATES  (4 * HIDDEN)   // 2048
#define MROWS  (SEQT * BATCH) // 2048
#define KDIM   512

// ---------------- scratch (device globals; no allocation allowed) -------------
__device__ __align__(16) float g_xgates[MROWS * GATES];     // xg[t*B+b][g]
__device__ __align__(16) float g_h[BATCH * HIDDEN];
__device__ __align__(16) float g_c[BATCH * HIDDEN];
__device__ int g_cap_is64;

// split-bf16 operand storage
__device__ __align__(16) __nv_bfloat16 g_xs_hi[MROWS * EMBED];
__device__ __align__(16) __nv_bfloat16 g_xs_lo[MROWS * EMBED];
__device__ __align__(16) __nv_bfloat16 g_hs_hi[MROWS * HIDDEN];
__device__ __align__(16) __nv_bfloat16 g_hs_lo[MROWS * HIDDEN];
__device__ __align__(16) __nv_bfloat16 g_Wih_hi[GATES * EMBED];
__device__ __align__(16) __nv_bfloat16 g_Wih_lo[GATES * EMBED];
__device__ __align__(16) __nv_bfloat16 g_Wfc_hi[VOCAB * HIDDEN];
__device__ __align__(16) __nv_bfloat16 g_Wfc_lo[VOCAB * HIDDEN];

// ---------------- helpers -----------------------------------------------------
__device__ __forceinline__ uint2 cvt_hilo(float x0, float x1) {
    __nv_bfloat162 h = __floats2bfloat162_rn(x0, x1);
    float2 hf = __bfloat1622float2(h);
    __nv_bfloat162 l = __floats2bfloat162_rn(x0 - hf.x, x1 - hf.y);
    uint2 o;
    o.x = *(uint32_t*)&h;
    o.y = *(uint32_t*)&l;
    return o;
}

// ---------------- captions dtype detection ------------------------------------
__global__ void detect_captions_kernel(const void* __restrict__ captions)
{
    const long long* c64 = (const long long*)captions;
    int bad = 0;
    for (int i = threadIdx.x; i < BATCH * SEQT; i += 32) {
        long long v = c64[i];
        if (v < 0 || v >= VOCAB) bad = 1;
    }
    #pragma unroll
    for (int s = 16; s > 0; s >>= 1)
        bad |= __shfl_xor_sync(0xffffffffu, bad, s);
    if (threadIdx.x == 0) g_cap_is64 = bad ? 0 : 1;
}

// ---------------- gather: build xs (directly as hi/lo bf16) --------------------
__global__ void gather_xs_kernel(const float* __restrict__ features,
                                 const void* __restrict__ captions,
                                 const float* __restrict__ emb_table)
{
    int m = blockIdx.x;
    int t = m >> 6;
    int b = m & 63;
    const float* src;
    if (t == 0) {
        src = features + (size_t)b * EMBED;
    } else {
        int idx = b * SEQT + (t - 1);
        long long tok = g_cap_is64 ? ((const long long*)captions)[idx]
                                   : (long long)((const int*)captions)[idx];
        if (tok < 0) tok = 0;
        if (tok >= VOCAB) tok = VOCAB - 1;
        src = emb_table + (size_t)tok * EMBED;
    }
    float4 v = ((const float4*)src)[threadIdx.x];
    uint2 p0 = cvt_hilo(v.x, v.y);
    uint2 p1 = cvt_hilo(v.z, v.w);
    size_t off = (size_t)m * EMBED + threadIdx.x * 4;   // halfs
    *(uint2*)(g_xs_hi + off) = make_uint2(p0.x, p1.x);
    *(uint2*)(g_xs_lo + off) = make_uint2(p0.y, p1.y);
}

// ---------------- fp32 -> bf16 hi/lo split convert (weights) -------------------
__global__ void split_convert_kernel(const float* __restrict__ src,
                                     __nv_bfloat16* __restrict__ hi,
                                     __nv_bfloat16* __restrict__ lo, int n4)
{
    int i = blockIdx.x * blockDim.x + threadIdx.x;
    if (i < n4) {
        float4 v = ((const float4*)src)[i];
        uint2 p0 = cvt_hilo(v.x, v.y);
        uint2 p1 = cvt_hilo(v.z, v.w);
        *(uint2*)(hi + (size_t)i * 4) = make_uint2(p0.x, p1.x);
        *(uint2*)(lo + (size_t)i * 4) = make_uint2(p0.y, p1.y);
    }
}

// =============== mma.sync split-bf16 GEMM: C = A * B^T (+bias) =================
// A: 2048 x 512 (hi/lo bf16 row-major).  B: N x 512 (hi/lo bf16 row-major).
// CTA tile 128x128, 8 warps (2x4) of 64x32, K chunked by 32.
// 3 passes per chunk: Ahi*Bhi + Ahi*Blo + Alo*Bhi, fp32 accum.
// mode 0: C[m*N+n]   mode 1: m=t*64+b -> C[(b*32+t)*N+n]

#define SSTR 40   // padded smem row stride in halfs (conflict-free)

#define MMA_BF16(d, a, b) \
    asm volatile("mma.sync.aligned.m16n8k16.row.col.f32.bf16.bf16.f32 " \
        "{%0,%1,%2,%3}, {%4,%5,%6,%7}, {%8,%9}, {%0,%1,%2,%3};" \
        : "+f"((d)[0]), "+f"((d)[1]), "+f"((d)[2]), "+f"((d)[3]) \
        : "r"((a)[0]), "r"((a)[1]), "r"((a)[2]), "r"((a)[3]), \
          "r"((b)[0]), "r"((b)[1]))

__global__ void __launch_bounds__(256) gemm_mma_kernel(
    const __nv_bfloat16* __restrict__ Ahi, const __nv_bfloat16* __restrict__ Alo,
    const __nv_bfloat16* __restrict__ Bhi, const __nv_bfloat16* __restrict__ Blo,
    float* __restrict__ C, int N,
    const float* __restrict__ bias1, const float* __restrict__ bias2, int mode)
{
    __shared__ __nv_bfloat16 sAh[128 * SSTR];
    __shared__ __nv_bfloat16 sAl[128 * SSTR];
    __shared__ __nv_bfloat16 sBh[128 * SSTR];
    __shared__ __nv_bfloat16 sBl[128 * SSTR];

    const int tid  = threadIdx.x;
    const int wid  = tid >> 5;
    const int lane = tid & 31;
    const int gq   = lane >> 2;     // 0..7
    const int tq   = lane & 3;      // 0..3
    const int m0 = blockIdx.y * 128;
    const int n0 = blockIdx.x * 128;
    const int wm = (wid & 1) * 64;   // warp m offset in tile
    const int wn = (wid >> 1) * 32;  // warp n offset in tile

    float acc[4][4][4];
    #pragma unroll
    for (int mi = 0; mi < 4; mi++)
        #pragma unroll
        for (int ni = 0; ni < 4; ni++)
            #pragma unroll
            for (int r = 0; r < 4; r++) acc[mi][ni][r] = 0.0f;

    // global tile load mapping: 256 thr, each loads 16 halfs of each array
    const int lr = tid >> 1;            // row 0..127
    const int lc = (tid & 1) * 16;      // 0 or 16
    const bool bvalid = (n0 + lr) < N;
    const uint4 zz = make_uint4(0, 0, 0, 0);

    for (int k0 = 0; k0 < KDIM; k0 += 32) {
        {
            const __nv_bfloat16* pah = Ahi + (size_t)(m0 + lr) * KDIM + k0 + lc;
            const __nv_bfloat16* pal = Alo + (size_t)(m0 + lr) * KDIM + k0 + lc;
            uint4 a0 = ((const uint4*)pah)[0];
            uint4 a1 = ((const uint4*)pah)[1];
            uint4 l0 = ((const uint4*)pal)[0];
            uint4 l1 = ((const uint4*)pal)[1];
            *(uint4*)(sAh + lr * SSTR + lc)     = a0;
            *(uint4*)(sAh + lr * SSTR + lc + 8) = a1;
            *(uint4*)(sAl + lr * SSTR + lc)     = l0;
            *(uint4*)(sAl + lr * SSTR + lc + 8) = l1;

            const __nv_bfloat16* pbh = Bhi + (size_t)(n0 + lr) * KDIM + k0 + lc;
            const __nv_bfloat16* pbl = Blo + (size_t)(n0 + lr) * KDIM + k0 + lc;
            uint4 b0 = bvalid ? ((const uint4*)pbh)[0] : zz;
            uint4 b1 = bvalid ? ((const uint4*)pbh)[1] : zz;
            uint4 c0 = bvalid ? ((const uint4*)pbl)[0] : zz;
            uint4 c1 = bvalid ? ((const uint4*)pbl)[1] : zz;
            *(uint4*)(sBh + lr * SSTR + lc)     = b0;
            *(uint4*)(sBh + lr * SSTR + lc + 8) = b1;
            *(uint4*)(sBl + lr * SSTR + lc)     = c0;
            *(uint4*)(sBl + lr * SSTR + lc + 8) = c1;
        }
        __syncthreads();

        #pragma unroll
        for (int ko = 0; ko < 32; ko += 16) {
            uint32_t af[4][4];
            uint32_t bf[4][2];
            const int abase = (wm + gq) * SSTR + ko + 2 * tq;
            const int bbase = (wn + gq) * SSTR + ko + 2 * tq;

            // ---- A-hi fragments ----
            #pragma unroll
            for (int mi = 0; mi < 4; mi++) {
                const int o = abase + mi * 16 * SSTR;
                af[mi][0] = *(const uint32_t*)(sAh + o);
                af[mi][1] = *(const uint32_t*)(sAh + o + 8 * SSTR);
                af[mi][2] = *(const uint32_t*)(sAh + o + 8);
                af[mi][3] = *(const uint32_t*)(sAh + o + 8 * SSTR + 8);
            }
            // ---- B-hi: hi*hi ----
            #pragma unroll
            for (int ni = 0; ni < 4; ni++) {
                const int o = bbase + ni * 8 * SSTR;
                bf[ni][0] = *(const uint32_t*)(sBh + o);
                bf[ni][1] = *(const uint32_t*)(sBh + o + 8);
            }
            #pragma unroll
            for (int mi = 0; mi < 4; mi++)
                #pragma unroll
                for (int ni = 0; ni < 4; ni++)
                    MMA_BF16(acc[mi][ni], af[mi], bf[ni]);

            // ---- B-lo: hi*lo ----
            #pragma unroll
            for (int ni = 0; ni < 4; ni++) {
                const int o = bbase + ni * 8 * SSTR;
                bf[ni][0] = *(const uint32_t*)(sBl + o);
                bf[ni][1] = *(const uint32_t*)(sBl + o + 8);
            }
            #pragma unroll
            for (int mi = 0; mi < 4; mi++)
                #pragma unroll
                for (int ni = 0; ni < 4; ni++)
                    MMA_BF16(acc[mi][ni], af[mi], bf[ni]);

            // ---- A-lo with B-hi: lo*hi ----
            #pragma unroll
            for (int mi = 0; mi < 4; mi++) {
                const int o = abase + mi * 16 * SSTR;
                af[mi][0] = *(const uint32_t*)(sAl + o);
                af[mi][1] = *(const uint32_t*)(sAl + o + 8 * SSTR);
                af[mi][2] = *(const uint32_t*)(sAl + o + 8);
                af[mi][3] = *(const uint32_t*)(sAl + o + 8 * SSTR + 8);
            }
            #pragma unroll
            for (int ni = 0; ni < 4; ni++) {
                const int o = bbase + ni * 8 * SSTR;
                bf[ni][0] = *(const uint32_t*)(sBh + o);
                bf[ni][1] = *(const uint32_t*)(sBh + o + 8);
            }
            #pragma unroll
            for (int mi = 0; mi < 4; mi++)
                #pragma unroll
                for (int ni = 0; ni < 4; ni++)
                    MMA_BF16(acc[mi][ni], af[mi], bf[ni]);
        }
        __syncthreads();
    }

    // ---- epilogue: bias + optional (b,t) permute, float2 stores ---------------
    #pragma unroll
    for (int mi = 0; mi < 4; mi++) {
        const int row = m0 + wm + mi * 16 + gq;
        size_t or0, or1;
        if (mode == 0) {
            or0 = (size_t)row;
            or1 = (size_t)(row + 8);
        } else {
            or0 = (size_t)((row & 63) * SEQT + (row >> 6));
            int r1 = row + 8;
            or1 = (size_t)((r1 & 63) * SEQT + (r1 >> 6));
        }
        #pragma unroll
        for (int ni = 0; ni < 4; ni++) {
            const int col = n0 + wn + ni * 8 + 2 * tq;
            if (col < N) {
                float bv0 = bias1[col], bv1 = bias1[col + 1];
                if (bias2) { bv0 += bias2[col]; bv1 += bias2[col + 1]; }
                float2 v0 = make_float2(acc[mi][ni][0] + bv0, acc[mi][ni][1] + bv1);
                float2 v1 = make_float2(acc[mi][ni][2] + bv0, acc[mi][ni][3] + bv1);
                *(float2*)(C + or0 * (size_t)N + col) = v0;
                *(float2*)(C + or1 * (size_t)N + col) = v1;
            }
        }
    }
}

// ---------------- fused LSTM step (fp32, writes hs as hi/lo bf16) --------------
__device__ __forceinline__ float sigmoidf_(float x) {
    return 1.0f / (1.0f + expf(-x));
}

__global__ void lstm_step_kernel(const float* __restrict__ W_hh, int t)
{
    const int tx = threadIdx.x & 31;
    const int ty = threadIdx.x >> 5;
    const int j  = blockIdx.x * 32 + tx;
    const int b0 = blockIdx.y * 16;

    float acc[4][4];
    #pragma unroll
    for (int g = 0; g < 4; g++)
        #pragma unroll
        for (int r = 0; r < 4; r++) acc[g][r] = 0.0f;

    if (t > 0) {
        __shared__ float hsh[16][33];
        __shared__ float wsh[128][33];

        for (int k0 = 0; k0 < HIDDEN; k0 += 32) {
            {
                int idx = threadIdx.x;
                int bb = idx >> 3;
                int kq = (idx & 7) * 4;
                float4 v = *(const float4*)&g_h[(size_t)(b0 + bb) * HIDDEN + k0 + kq];
                hsh[bb][kq + 0] = v.x; hsh[bb][kq + 1] = v.y;
                hsh[bb][kq + 2] = v.z; hsh[bb][kq + 3] = v.w;
            }
            #pragma unroll
            for (int e = 0; e < 8; e++) {
                int idx = threadIdx.x + 128 * e;
                int row = idx >> 3;
                int kq  = (idx & 7) * 4;
                int g   = row >> 5;
                int jl  = row & 31;
                int grow = g * HIDDEN + blockIdx.x * 32 + jl;
                float4 v = *(const float4*)&W_hh[(size_t)grow * HIDDEN + k0 + kq];
                wsh[row][kq + 0] = v.x; wsh[row][kq + 1] = v.y;
                wsh[row][kq + 2] = v.z; wsh[row][kq + 3] = v.w;
            }
            __syncthreads();

            #pragma unroll
            for (int kk = 0; kk < 32; kk++) {
                float hv[4];
                #pragma unroll
                for (int r = 0; r < 4; r++) hv[r] = hsh[ty * 4 + r][kk];
                #pragma unroll
                for (int g = 0; g < 4; g++) {
                    float wv = wsh[g * 32 + tx][kk];
                    #pragma unroll
                    for (int r = 0; r < 4; r++)
                        acc[g][r] = fmaf(wv, hv[r], acc[g][r]);
                }
            }
            __syncthreads();
        }
    }

    const float* xg = g_xgates + (size_t)t * BATCH * GATES;

    #pragma unroll
    for (int r = 0; r < 4; r++) {
        int b = b0 + ty * 4 + r;
        size_t gbase = (size_t)b * GATES + j;
        float gi = acc[0][r] + xg[gbase];
        float gf = acc[1][r] + xg[gbase + HIDDEN];
        float gg = acc[2][r] + xg[gbase + 2 * HIDDEN];
        float go = acc[3][r] + xg[gbase + 3 * HIDDEN];

        float i_ = sigmoidf_(gi);
        float f_ = sigmoidf_(gf);
        float g_ = tanhf(gg);
        float o_ = sigmoidf_(go);

        size_t hidx = (size_t)b * HIDDEN + j;
        float cold = (t == 0) ? 0.0f : g_c[hidx];
        float cn = f_ * cold + i_ * g_;
        float hn = o_ * tanhf(cn);
        g_c[hidx] = cn;
        g_h[hidx] = hn;

        // hs in split-bf16 for the FC GEMM
        size_t off = (size_t)t * BATCH * HIDDEN + hidx;
        __nv_bfloat16 hh = __float2bfloat16(hn);
        g_hs_hi[off] = hh;
        g_hs_lo[off] = __float2bfloat16(hn - __bfloat162float(hh));
    }
}

// ---------------- launch ------------------------------------------------------
extern "C" void kernel_launch(void* const* d_in, const int* in_sizes, int n_in,
                              void* d_out, int out_size)
{
    const float* features  = (const float*)d_in[0];
    const void*  captions  = d_in[1];
    const float* emb_table = (const float*)d_in[2];
    const float* W_ih      = (const float*)d_in[3];
    const float* W_hh      = (const float*)d_in[4];
    const float* b_ih      = (const float*)d_in[5];
    const float* b_hh      = (const float*)d_in[6];
    const float* W_fc      = (const float*)d_in[7];
    const float* b_fc      = (const float*)d_in[8];
    float*       out       = (float*)d_out;

    float* xg_p;  cudaGetSymbolAddress((void**)&xg_p, g_xgates);
    __nv_bfloat16 *xsh, *xsl, *hsh, *hsl, *wih_h, *wih_l, *wfc_h, *wfc_l;
    cudaGetSymbolAddress((void**)&xsh, g_xs_hi);
    cudaGetSymbolAddress((void**)&xsl, g_xs_lo);
    cudaGetSymbolAddress((void**)&hsh, g_hs_hi);
    cudaGetSymbolAddress((void**)&hsl, g_hs_lo);
    cudaGetSymbolAddress((void**)&wih_h, g_Wih_hi);
    cudaGetSymbolAddress((void**)&wih_l, g_Wih_lo);
    cudaGetSymbolAddress((void**)&wfc_h, g_Wfc_hi);
    cudaGetSymbolAddress((void**)&wfc_l, g_Wfc_lo);

    // 0) captions dtype detection
    detect_captions_kernel<<<1, 32>>>(captions);

    // 1) gather xs (split-bf16)
    gather_xs_kernel<<<MROWS, 128>>>(features, captions, emb_table);

    // 2) split weights
    {
        int n4 = GATES * EMBED / 4;
        split_convert_kernel<<<(n4 + 255) / 256, 256>>>(W_ih, wih_h, wih_l, n4);
        n4 = VOCAB * HIDDEN / 4;
        split_convert_kernel<<<(n4 + 255) / 256, 256>>>(W_fc, wfc_h, wfc_l, n4);
    }

    // 3) x_gates = xs @ W_ih^T + b_ih + b_hh  (tensor core, split-bf16)
    {
        dim3 grid(GATES / 128, MROWS / 128);
        gemm_mma_kernel<<<grid, 256>>>(xsh, xsl, wih_h, wih_l, xg_p,
                                       GATES, b_ih, b_hh, 0);
    }

    // 4) 32 recurrent steps
    {
        dim3 grid(HIDDEN / 32, BATCH / 16);
        for (int t = 0; t < SEQT; t++)
            lstm_step_kernel<<<grid, 128>>>(W_hh, t);
    }

    // 5) logits = hs @ W_fc^T + b_fc, permuted to (b, t, v)
    {
        dim3 grid((VOCAB + 127) / 128, MROWS / 128);
        gemm_mma_kernel<<<grid, 256>>>(hsh, hsl, wfc_h, wfc_l, out,
                                       VOCAB, b_fc, nullptr, 1);
    }
}